// round 1
// baseline (speedup 1.0000x reference)
#include <cuda_runtime.h>
#include <math_constants.h>

// Analytic collapse of the 18-qubit circuit:
//   theta_{b,i} = (x_{b,i} - min(x)) / (max(x) - min(x)) * 2*pi - pi   (global min/max over the 64x18 batch)
//   <Z_i>_b = cos(a_i)cos(b_i) * cos(theta_{b,i})
//           - sin(b_i) * sin(theta_{b,i}) * cos(theta_{b,i-1}) * cos(theta_{b,i+1})
//   out_b = sum_i head_w[i] * <Z_i>_b + head_b
// (RZ angle gamma drops out of <Z>; CZ-ladder conjugation of the off-diagonal
//  term contributes the neighbor cos factors; boundary neighbors contribute 1.)

#define NW 18
#define NB 64
#define NT 128

__global__ void qcircuit_analytic_kernel(const float* __restrict__ sb,
                                         const float* __restrict__ params,
                                         const float* __restrict__ hw,
                                         const float* __restrict__ hb,
                                         float* __restrict__ out) {
    __shared__ float smin[NT], smax[NT];
    __shared__ float cA[NW], sB[NW], wgt[NW];

    const int t = threadIdx.x;

    // ---- global min/max over all B*n = 1152 inputs ----
    float mn = CUDART_INF_F, mx = -CUDART_INF_F;
    for (int i = t; i < NB * NW; i += NT) {
        float v = sb[i];
        mn = fminf(mn, v);
        mx = fmaxf(mx, v);
    }
    smin[t] = mn;
    smax[t] = mx;

    // ---- per-wire constants ----
    if (t < NW) {
        float alpha = params[t * 3 + 0];
        float beta  = params[t * 3 + 1];
        cA[t]  = cosf(alpha) * cosf(beta);
        sB[t]  = sinf(beta);
        wgt[t] = hw[t];
    }
    __syncthreads();

    for (int s = NT / 2; s > 0; s >>= 1) {
        if (t < s) {
            smin[t] = fminf(smin[t], smin[t + s]);
            smax[t] = fmaxf(smax[t], smax[t + s]);
        }
        __syncthreads();
    }

    const float gmin = smin[0];
    const float gmax = smax[0];
    const float inv_range = 1.0f / (gmax - gmin);

    // ---- one thread per batch row ----
    if (t < NB) {
        float cz[NW], sz[NW];
#pragma unroll
        for (int i = 0; i < NW; i++) {
            float theta = (sb[t * NW + i] - gmin) * inv_range * (2.0f * CUDART_PI_F)
                          - CUDART_PI_F;
            sincosf(theta, &sz[i], &cz[i]);
        }
        float acc = hb[0];
#pragma unroll
        for (int i = 0; i < NW; i++) {
            float zl = (i == 0)      ? 1.0f : cz[i - 1];
            float zr = (i == NW - 1) ? 1.0f : cz[i + 1];
            acc += wgt[i] * (cA[i] * cz[i] - sB[i] * sz[i] * zl * zr);
        }
        out[t] = acc;
    }
}

extern "C" void kernel_launch(void* const* d_in, const int* in_sizes, int n_in,
                              void* d_out, int out_size) {
    const float* state_batch = (const float*)d_in[0]; // (64, 18)
    const float* params      = (const float*)d_in[1]; // (18, 3)
    const float* head_w      = (const float*)d_in[2]; // (1, 18)
    const float* head_b      = (const float*)d_in[3]; // (1,)
    float* out = (float*)d_out;                       // (64,)

    qcircuit_analytic_kernel<<<1, NT>>>(state_batch, params, head_w, head_b, out);
}

// round 2
// speedup vs baseline: 1.3023x; 1.3023x over previous
#include <cuda_runtime.h>
#include <math_constants.h>

// Analytic collapse of the 18-qubit circuit (derivation in R1):
//   theta_{b,i} = (x_{b,i} - min(x)) / (max(x) - min(x)) * 2*pi - pi
//   <Z_i>_b = cos(a_i)cos(b_i)*cos(th_i) - sin(b_i)*sin(th_i)*cos(th_{i-1})*cos(th_{i+1})
//   out_b = sum_i head_w[i] * <Z_i>_b + head_b
// R2: fast MUFU trig, warp-shuffle reduction (1 barrier), float4 staged loads.

#define NW 18
#define NB 64
#define NT 128
#define NELEM (NB * NW)   // 1152
#define NVEC  (NELEM / 4) // 288

__global__ void __launch_bounds__(NT, 1)
qcircuit_analytic_kernel(const float* __restrict__ sb,
                         const float* __restrict__ params,
                         const float* __restrict__ hw,
                         const float* __restrict__ hb,
                         float* __restrict__ out) {
    __shared__ float sdata[NELEM];
    __shared__ float cA[NW], sB[NW], wgt[NW];
    __shared__ float wmin[4], wmax[4];

    const int t    = threadIdx.x;
    const int lane = t & 31;
    const int wid  = t >> 5;

    // ---- staged vector load + thread-local min/max ----
    const float4* sb4 = (const float4*)sb;
    float4* sd4 = (float4*)sdata;
    float mn = CUDART_INF_F, mx = -CUDART_INF_F;
#pragma unroll
    for (int k = 0; k < 3; k++) {
        int idx = t + k * NT;
        if (idx < NVEC) {
            float4 v = sb4[idx];
            sd4[idx] = v;
            mn = fminf(fminf(fminf(v.x, v.y), fminf(v.z, v.w)), mn);
            mx = fmaxf(fmaxf(fmaxf(v.x, v.y), fmaxf(v.z, v.w)), mx);
        }
    }

    // ---- per-wire constants (overlaps with loads above) ----
    if (t >= NT - NW) {  // last warp's low lanes handle constants
        int w = t - (NT - NW);
        float alpha = params[w * 3 + 0];
        float beta  = params[w * 3 + 1];
        cA[w]  = __cosf(alpha) * __cosf(beta);
        sB[w]  = __sinf(beta);
        wgt[w] = hw[w];
    }

    // ---- warp-level min/max reduce ----
#pragma unroll
    for (int s = 16; s > 0; s >>= 1) {
        mn = fminf(mn, __shfl_xor_sync(0xFFFFFFFFu, mn, s));
        mx = fmaxf(mx, __shfl_xor_sync(0xFFFFFFFFu, mx, s));
    }
    if (lane == 0) { wmin[wid] = mn; wmax[wid] = mx; }
    __syncthreads();

    const float gmin = fminf(fminf(wmin[0], wmin[1]), fminf(wmin[2], wmin[3]));
    const float gmax = fmaxf(fmaxf(wmax[0], wmax[1]), fmaxf(wmax[2], wmax[3]));
    const float scale = (2.0f * CUDART_PI_F) / (gmax - gmin);

    // ---- one thread per batch row, all reads from smem ----
    if (t < NB) {
        float cz[NW], sz[NW];
#pragma unroll
        for (int i = 0; i < NW; i++) {
            float theta = (sdata[t * NW + i] - gmin) * scale - CUDART_PI_F;
            __sincosf(theta, &sz[i], &cz[i]);
        }
        float acc = hb[0];
#pragma unroll
        for (int i = 0; i < NW; i++) {
            float zl = (i == 0)      ? 1.0f : cz[i - 1];
            float zr = (i == NW - 1) ? 1.0f : cz[i + 1];
            acc = fmaf(wgt[i], fmaf(cA[i], cz[i], -sB[i] * sz[i] * zl * zr), acc);
        }
        out[t] = acc;
    }
}

extern "C" void kernel_launch(void* const* d_in, const int* in_sizes, int n_in,
                              void* d_out, int out_size) {
    const float* state_batch = (const float*)d_in[0]; // (64, 18)
    const float* params      = (const float*)d_in[1]; // (18, 3)
    const float* head_w      = (const float*)d_in[2]; // (1, 18)
    const float* head_b      = (const float*)d_in[3]; // (1,)
    float* out = (float*)d_out;                       // (64,)

    qcircuit_analytic_kernel<<<1, NT>>>(state_batch, params, head_w, head_b, out);
}

// round 3
// speedup vs baseline: 1.3462x; 1.0337x over previous
#include <cuda_runtime.h>
#include <math_constants.h>

// Analytic collapse of the 18-qubit circuit (derivation in R1):
//   theta_{b,i} = (x_{b,i} - min(x)) / (max(x) - min(x)) * 2*pi - pi
//   <Z_i>_b = cos(a_i)cos(b_i)*cos(th_i) - sin(b_i)*sin(th_i)*cos(th_{i-1})*cos(th_{i+1})
//   out_b = sum_i head_w[i] * <Z_i>_b + head_b
// R3: one block per batch row (64 blocks across SMs); each block redundantly
// computes the global min/max (input is only 4.6KB), killing the single-SM
// MUFU throughput bottleneck. Warp 0 lanes 0..17 finish the row via shuffles.

#define NW 18
#define NB 64
#define NT 128
#define NELEM (NB * NW)   // 1152
#define NVEC  (NELEM / 4) // 288

__global__ void __launch_bounds__(NT, 1)
qcircuit_analytic_kernel(const float* __restrict__ sb,
                         const float* __restrict__ params,
                         const float* __restrict__ hw,
                         const float* __restrict__ hb,
                         float* __restrict__ out) {
    __shared__ float wmin[4], wmax[4];
    __shared__ float cA[NW], sB[NW], wgt[NW];

    const int t    = threadIdx.x;
    const int lane = t & 31;
    const int wid  = t >> 5;
    const int row  = blockIdx.x;

    // ---- every block: full min/max over all 1152 inputs (float4) ----
    const float4* sb4 = (const float4*)sb;
    float mn = CUDART_INF_F, mx = -CUDART_INF_F;
#pragma unroll
    for (int k = 0; k < 3; k++) {
        int idx = t + k * NT;
        if (idx < NVEC) {
            float4 v = sb4[idx];
            mn = fminf(fminf(fminf(v.x, v.y), fminf(v.z, v.w)), mn);
            mx = fmaxf(fmaxf(fmaxf(v.x, v.y), fmaxf(v.z, v.w)), mx);
        }
    }

    // ---- per-wire constants on warp 1 (overlaps the reduce) ----
    if (wid == 1 && lane < NW) {
        int w = lane;
        cA[w]  = __cosf(params[w * 3 + 0]) * __cosf(params[w * 3 + 1]);
        sB[w]  = __sinf(params[w * 3 + 1]);
        wgt[w] = hw[w];
    }

    // ---- warp min/max reduce, then cross-warp via smem (1 barrier) ----
#pragma unroll
    for (int s = 16; s > 0; s >>= 1) {
        mn = fminf(mn, __shfl_xor_sync(0xFFFFFFFFu, mn, s));
        mx = fmaxf(mx, __shfl_xor_sync(0xFFFFFFFFu, mx, s));
    }
    if (lane == 0) { wmin[wid] = mn; wmax[wid] = mx; }
    __syncthreads();

    // ---- warp 0, lanes 0..17: one wire each for this block's row ----
    if (wid == 0) {
        const float gmin  = fminf(fminf(wmin[0], wmin[1]), fminf(wmin[2], wmin[3]));
        const float gmax  = fmaxf(fmaxf(wmax[0], wmax[1]), fmaxf(wmax[2], wmax[3]));
        const float scale = (2.0f * CUDART_PI_F) / (gmax - gmin);

        int idx = row * NW + lane;
        if (idx > NELEM - 1) idx = NELEM - 1;   // lanes >= NW: harmless in-bounds read
        float theta = (sb[idx] - gmin) * scale - CUDART_PI_F;   // L1 hit (warm)
        float sz, cz;
        __sincosf(theta, &sz, &cz);

        float zl = __shfl_up_sync(0xFFFFFFFFu, cz, 1);    // cz[i-1]
        float zr = __shfl_down_sync(0xFFFFFFFFu, cz, 1);  // cz[i+1]
        if (lane == 0)      zl = 1.0f;
        if (lane == NW - 1) zr = 1.0f;

        float term = 0.0f;
        if (lane < NW)
            term = wgt[lane] * fmaf(cA[lane], cz, -sB[lane] * sz * zl * zr);

        // sum over 32 lanes (lanes >= NW contribute 0)
#pragma unroll
        for (int s = 16; s > 0; s >>= 1)
            term += __shfl_xor_sync(0xFFFFFFFFu, term, s);

        if (lane == 0) out[row] = term + hb[0];
    }
}

extern "C" void kernel_launch(void* const* d_in, const int* in_sizes, int n_in,
                              void* d_out, int out_size) {
    const float* state_batch = (const float*)d_in[0]; // (64, 18)
    const float* params      = (const float*)d_in[1]; // (18, 3)
    const float* head_w      = (const float*)d_in[2]; // (1, 18)
    const float* head_b      = (const float*)d_in[3]; // (1,)
    float* out = (float*)d_out;                       // (64,)

    qcircuit_analytic_kernel<<<NB, NT>>>(state_batch, params, head_w, head_b, out);
}